// round 14
// baseline (speedup 1.0000x reference)
#include <cuda_runtime.h>
#include <cstdint>
#include <cstring>

#define Bt 4
#define Ht 192
#define Wt 192
#define HWt (Ht*Wt)
#define Qt 36864
#define PI_F 3.14159274f

// ---------------- scratch (device globals; no allocation allowed) ----------------
__device__ float g_t1[(size_t)Bt*128*HWt];      // adapter conv1 output (sin applied)
__device__ float g_feat[(size_t)Bt*9*HWt];      // [b][9][H][W]
__device__ float g_coefT[(size_t)Bt*HWt*256];   // [b][pix][256]
__device__ float g_freqT[(size_t)Bt*HWt*256];   // [b][pix][256]

// ---------------- f32x2 + cp.async helpers ----------------
__device__ __forceinline__ void fma2(unsigned long long& d, unsigned long long a, unsigned long long b) {
    asm("fma.rn.f32x2 %0, %1, %2, %0;" : "+l"(d) : "l"(a), "l"(b));
}
__device__ __forceinline__ unsigned long long dup2(float w) {
    unsigned long long r;
    asm("mov.b64 %0, {%1, %1};" : "=l"(r) : "f"(w));
    return r;
}
__device__ __forceinline__ unsigned long long pack2(float lo, float hi) {
    unsigned long long r;
    asm("mov.b64 %0, {%1, %2};" : "=l"(r) : "f"(lo), "f"(hi));
    return r;
}
__device__ __forceinline__ float lo2(unsigned long long v){ float2 f; memcpy(&f,&v,8); return f.x; }
__device__ __forceinline__ float hi2(unsigned long long v){ float2 f; memcpy(&f,&v,8); return f.y; }
__device__ __forceinline__ void cpa16(uint32_t s, const void* g) {
    asm volatile("cp.async.ca.shared.global [%0], [%1], 16;" :: "r"(s), "l"(g));
}
__device__ __forceinline__ void cpa_commit() { asm volatile("cp.async.commit_group;"); }
__device__ __forceinline__ void cpa_wait1() { asm volatile("cp.async.wait_group 1;"); }
__device__ __forceinline__ void cpa_wait0() { asm volatile("cp.async.wait_group 0;"); }

// ---------------- K1: adapter conv1: inp(3ch) -> sin(conv3x3) -> t1(128ch) ----------------
__global__ void k_adapter1(const float* __restrict__ inp,
                           const float* __restrict__ a1_w,
                           const float* __restrict__ a1_b)
{
    __shared__ float s_in[3][18][18];
    __shared__ float s_w[128*28];
    __shared__ float s_b[128];
    const int b = blockIdx.z;
    const int x0 = blockIdx.x*16, y0 = blockIdx.y*16;
    const int tx = threadIdx.x, ty = threadIdx.y;
    const int t = ty*16 + tx;

    for (int i = t; i < 128*27; i += 256) { int oc = i/27, r = i%27; s_w[oc*28+r] = a1_w[i]; }
    for (int i = t; i < 128; i += 256)    { s_b[i] = a1_b[i]; s_w[i*28+27] = 0.f; }
    for (int i = t; i < 3*18*18; i += 256) {
        int ic = i/324, r = i%324;
        int yy = y0 + r/18 - 1, xx = x0 + r%18 - 1;
        float v = 0.f;
        if (yy >= 0 && yy < Ht && xx >= 0 && xx < Wt)
            v = inp[((size_t)(b*3+ic))*HWt + (size_t)yy*Wt + xx];
        s_in[ic][r/18][r%18] = v;
    }
    __syncthreads();

    float f[28];
    #pragma unroll
    for (int ic = 0; ic < 3; ic++)
        #pragma unroll
        for (int ky = 0; ky < 3; ky++)
            #pragma unroll
            for (int kx = 0; kx < 3; kx++)
                f[ic*9 + ky*3 + kx] = s_in[ic][ty+ky][tx+kx];
    f[27] = 0.f;

    unsigned long long fp[14];
    #pragma unroll
    for (int j = 0; j < 14; j++) fp[j] = pack2(f[2*j], f[2*j+1]);

    const int x = x0 + tx, y = y0 + ty;
    const size_t obase = ((size_t)b*128)*HWt + (size_t)y*Wt + x;
    for (int oc = 0; oc < 128; oc++) {
        const ulonglong2* w2 = (const ulonglong2*)&s_w[oc*28];
        unsigned long long accA = 0ull, accB = 0ull;
        #pragma unroll
        for (int j = 0; j < 7; j++) {
            ulonglong2 w = w2[j];
            fma2(accA, w.x, fp[2*j]);
            fma2(accB, w.y, fp[2*j+1]);
        }
        float acc = s_b[oc] + lo2(accA) + hi2(accA) + lo2(accB) + hi2(accB);
        g_t1[obase + (size_t)oc*HWt] = __sinf(acc);
    }
}

// ---------------- K2: adapter conv2 (128->3) + sin, build feat[9] ----------------
__global__ void k_adapter2_feat(const float* __restrict__ inp,
                                const float* __restrict__ score,
                                const float* __restrict__ a2_w,
                                const float* __restrict__ a2_b)
{
    __shared__ float s_t[16][18][18];
    __shared__ float s_w[3*128*12];
    const int b = blockIdx.z;
    const int x0 = blockIdx.x*16, y0 = blockIdx.y*16;
    const int tx = threadIdx.x, ty = threadIdx.y;
    const int t = ty*16 + tx;

    for (int i = t; i < 3*128*9; i += 256) { int oi = i/9, r = i%9; s_w[oi*12+r] = a2_w[i]; }
    for (int i = t; i < 3*128; i += 256)   { s_w[i*12+9]=0.f; s_w[i*12+10]=0.f; s_w[i*12+11]=0.f; }

    float acc0 = a2_b[0], acc1 = a2_b[1], acc2 = a2_b[2];

    for (int ic0 = 0; ic0 < 128; ic0 += 16) {
        __syncthreads();
        for (int i = t; i < 16*324; i += 256) {
            int ic = i/324, r = i%324;
            int yy = y0 + r/18 - 1, xx = x0 + r%18 - 1;
            float v = 0.f;
            if (yy >= 0 && yy < Ht && xx >= 0 && xx < Wt)
                v = g_t1[((size_t)(b*128 + ic0 + ic))*HWt + (size_t)yy*Wt + xx];
            s_t[ic][r/18][r%18] = v;
        }
        __syncthreads();
        #pragma unroll
        for (int ic = 0; ic < 16; ic++) {
            float f[12];
            #pragma unroll
            for (int ky = 0; ky < 3; ky++)
                #pragma unroll
                for (int kx = 0; kx < 3; kx++)
                    f[ky*3+kx] = s_t[ic][ty+ky][tx+kx];
            f[9] = f[10] = f[11] = 0.f;
            unsigned long long fp[6];
            #pragma unroll
            for (int j = 0; j < 6; j++) fp[j] = pack2(f[2*j], f[2*j+1]);
            #pragma unroll
            for (int oc = 0; oc < 3; oc++) {
                const ulonglong2* w2 = (const ulonglong2*)&s_w[(oc*128 + ic0 + ic)*12];
                unsigned long long aA = 0ull, aB = 0ull;
                #pragma unroll
                for (int j = 0; j < 3; j++) {
                    ulonglong2 w = w2[j];
                    fma2(aA, w.x, fp[2*j]);
                    fma2(aB, w.y, fp[2*j+1]);
                }
                float a = lo2(aA) + hi2(aA) + lo2(aB) + hi2(aB);
                if (oc == 0) acc0 += a; else if (oc == 1) acc1 += a; else acc2 += a;
            }
        }
    }

    const int x = x0 + tx, y = y0 + ty;
    const size_t pix = (size_t)y*Wt + x;
    const size_t fb = (size_t)b*9*HWt;
    #pragma unroll
    for (int c = 0; c < 3; c++) {
        g_feat[fb + (size_t)c*HWt + pix]       = inp[((size_t)(b*3+c))*HWt + pix];
        g_feat[fb + (size_t)(3+c)*HWt + pix]   = score[((size_t)(b*3+c))*HWt + pix];
    }
    g_feat[fb + (size_t)6*HWt + pix] = __sinf(acc0);
    g_feat[fb + (size_t)7*HWt + pix] = __sinf(acc1);
    g_feat[fb + (size_t)8*HWt + pix] = __sinf(acc2);
}

// ---------------- K3: coef + freq conv (9 -> 512), 256 threads, 8-row ILP ----------------
#define K3_SMEM (512*84*4 + 512*4)
__global__ void __launch_bounds__(256) k_coef_freq(
    const float* __restrict__ coef_w, const float* __restrict__ coef_b,
    const float* __restrict__ freq_w, const float* __restrict__ freq_b)
{
    extern __shared__ float sm[];
    float* s_w = sm;           // [512][84]
    float* s_b = sm + 512*84;  // [512]
    const int b = blockIdx.z;
    const int x0 = blockIdx.x*16, y0 = blockIdx.y*16;
    const int t = threadIdx.y*16 + threadIdx.x;

    for (int i = t; i < 256*81; i += 256) {
        int oc = i/81, r = i%81;
        s_w[oc*84 + r]       = coef_w[i];
        s_w[(256+oc)*84 + r] = freq_w[i];
    }
    for (int i = t; i < 512; i += 256) {
        s_w[i*84+81] = 0.f; s_w[i*84+82] = 0.f; s_w[i*84+83] = 0.f;
        s_b[i] = (i < 256) ? coef_b[i] : freq_b[i-256];
    }
    __syncthreads();

    const int x = x0 + threadIdx.x, y = y0 + threadIdx.y;
    float f[84];
    #pragma unroll
    for (int ic = 0; ic < 9; ic++)
        #pragma unroll
        for (int ky = 0; ky < 3; ky++)
            #pragma unroll
            for (int kx = 0; kx < 3; kx++) {
                int yy = y + ky - 1, xx = x + kx - 1;
                float v = 0.f;
                if (yy >= 0 && yy < Ht && xx >= 0 && xx < Wt)
                    v = g_feat[((size_t)(b*9+ic))*HWt + (size_t)yy*Wt + xx];
                f[ic*9 + ky*3 + kx] = v;
            }
    f[81] = f[82] = f[83] = 0.f;

    unsigned long long fp[42];
    #pragma unroll
    for (int j = 0; j < 42; j++) fp[j] = pack2(f[2*j], f[2*j+1]);

    const size_t pix = (size_t)y*Wt + x;
    const size_t obase = ((size_t)b*HWt + pix)*256;
    #pragma unroll
    for (int half = 0; half < 2; half++) {
        float* dst = half ? g_freqT : g_coefT;
        for (int oc = 0; oc < 256; oc += 8) {
            unsigned long long accA[8], accB[8];
            #pragma unroll
            for (int u = 0; u < 8; u++) { accA[u] = 0ull; accB[u] = 0ull; }
            #pragma unroll 7
            for (int j = 0; j < 21; j++) {
                #pragma unroll
                for (int u = 0; u < 8; u++) {
                    ulonglong2 w = *(const ulonglong2*)&s_w[(half*256 + oc + u)*84 + 4*j];
                    fma2(accA[u], w.x, fp[2*j]);
                    fma2(accB[u], w.y, fp[2*j+1]);
                }
            }
            float av[8];
            #pragma unroll
            for (int u = 0; u < 8; u++)
                av[u] = s_b[half*256 + oc + u]
                      + lo2(accA[u]) + hi2(accA[u]) + lo2(accB[u]) + hi2(accB[u]);
            *(float4*)&dst[obase + oc]     = make_float4(av[0], av[1], av[2], av[3]);
            *(float4*)&dst[obase + oc + 4] = make_float4(av[4], av[5], av[6], av[7]);
        }
    }
}

// ---------------- K4: per-query sin/cos + MLP + bilinear residual (round-12) ----------------
#define QB 64
#define KQ_SMEM ((256*64 + 2*256*20 + 256 + 768) * 4)

__global__ void __launch_bounds__(256, 2) k_query(
    const float* __restrict__ inp,
    const float* __restrict__ coord, const float* __restrict__ cell,
    const float* __restrict__ phase_w,
    const float* __restrict__ w0, const float* __restrict__ b0,
    const float* __restrict__ w1, const float* __restrict__ b1,
    const float* __restrict__ w2, const float* __restrict__ b2,
    const float* __restrict__ w3, const float* __restrict__ b3,
    const float* __restrict__ w4, const float* __restrict__ b4,
    float* __restrict__ out)
{
    extern __shared__ float sm[];
    float* sX   = sm;                    // 256*64
    float* sW0  = sX  + 256*64;          // 256*20
    float* sW1  = sW0 + 256*20;          // 256*20
    float* s_ph = sW1 + 256*20;          // 256
    float* s_w4 = s_ph + 256;            // 768

    const int t   = threadIdx.x;
    const int wid = t >> 5;
    const int l   = t & 31;
    const float* Ws[4] = {w0, w1, w2, w3};
    const float* Bs[4] = {b0, b1, b2, b3};

    auto stage = [&](const float* Wsrc, int tn, float* buf) {
        #pragma unroll
        for (int u = 0; u < 4; u++) {
            int c   = l + 32*u;
            int j   = c >> 2;
            int row = 4*wid + (j & 3) + 32*(j >> 2);
            int col = (c & 3)*4;
            cpa16((uint32_t)__cvta_generic_to_shared(&buf[row*20 + col]),
                  Wsrc + (size_t)row*256 + tn*16 + col);
        }
        cpa_commit();
    };

    stage(w0, 0, sW0);
    stage(w0, 1, sW1);

    s_ph[t] = phase_w[t];
    for (int i = t; i < 768; i += 256) s_w4[i] = w4[i];

    // ---- prologue: sincos features into sX[k][q] ----
    {
        const int q = t >> 2;
        const int ql = t & 3;
        const int gq = blockIdx.x*QB + q;
        const int b  = gq / Qt;

        const float cy = coord[(size_t)gq*2 + 0];
        const float cx = coord[(size_t)gq*2 + 1];
        const float ccy = fminf(fmaxf(cy, -0.999999f), 0.999999f);
        const float ccx = fminf(fmaxf(cx, -0.999999f), 0.999999f);
        const float fy = ((ccy + 1.f)*Ht - 1.f)*0.5f;
        const float fx = ((ccx + 1.f)*Wt - 1.f)*0.5f;
        const int iy = (int)fminf(fmaxf(rintf(fy), 0.f), (float)(Ht-1));
        const int ix = (int)fminf(fmaxf(rintf(fx), 0.f), (float)(Wt-1));
        const float qy = -1.f + (2.f*(float)iy + 1.f)/(float)Ht;
        const float qx = -1.f + (2.f*(float)ix + 1.f)/(float)Wt;
        const float rel0 = (cy - qy)*(float)Ht;
        const float rel1 = (cx - qx)*(float)Wt;
        const float rc0 = cell[(size_t)gq*2 + 0]*(float)Ht;
        const float rc1 = cell[(size_t)gq*2 + 1]*(float)Wt;
        const size_t base = ((size_t)b*HWt + (size_t)iy*Wt + ix)*256;

        __syncthreads();   // s_ph ready

        #pragma unroll
        for (int i = 0; i < 32; i++) {
            const int j = ql + 4*i;
            float2 fr = *(const float2*)&g_freqT[base + 2*j];
            float qf = fr.x*rel0 + fr.y*rel1 + s_ph[2*j]*rc0 + s_ph[2*j+1]*rc1;
            float sv, cv;
            __sincosf(PI_F*qf, &sv, &cv);
            float c0 = g_coefT[base + j];
            float c1 = g_coefT[base + 128 + j];
            sX[j*64 + q]         = c0*cv;
            sX[(128 + j)*64 + q] = c1*sv;
        }
    }
    __syncthreads();

    const int cg = t >> 3;               // 0..31 : channels cg, cg+32, ..., cg+224
    const int qg = t & 7;                // 0..7  : queries qg*4..+4 and 32+qg*4..+4

    #pragma unroll 1
    for (int L = 0; L < 4; L++) {
        const float* Bl = Bs[L];

        unsigned long long acc[8][4];
        #pragma unroll
        for (int i = 0; i < 8; i++)
            #pragma unroll
            for (int p = 0; p < 4; p++) acc[i][p] = 0ull;

        #pragma unroll 1
        for (int tile = 0; tile < 16; tile++) {
            const int g = L*16 + tile;
            if (g < 63) cpa_wait1();
            else        cpa_wait0();

            const float* sw = (g & 1) ? sW1 : sW0;
            const int kbase = tile*16;
            #pragma unroll
            for (int kk = 0; kk < 16; kk += 4) {
                float4 wv[8];
                #pragma unroll
                for (int i = 0; i < 8; i++)
                    wv[i] = *(const float4*)&sw[(cg + 32*i)*20 + kk];
                #pragma unroll
                for (int dk = 0; dk < 4; dk++) {
                    const int k = kbase + kk + dk;
                    ulonglong2 xa = *(const ulonglong2*)&sX[k*64 + qg*4];
                    ulonglong2 xb = *(const ulonglong2*)&sX[k*64 + 32 + qg*4];
                    #pragma unroll
                    for (int i = 0; i < 8; i++) {
                        float w = (dk == 0) ? wv[i].x : (dk == 1) ? wv[i].y
                                : (dk == 2) ? wv[i].z : wv[i].w;
                        unsigned long long wd = dup2(w);
                        fma2(acc[i][0], wd, xa.x);
                        fma2(acc[i][1], wd, xa.y);
                        fma2(acc[i][2], wd, xb.x);
                        fma2(acc[i][3], wd, xb.y);
                    }
                }
            }

            const int gn = g + 2;
            if (gn < 64)
                stage(Ws[gn >> 4], gn & 15, (g & 1) ? sW1 : sW0);
        }

        __syncthreads();   // all warps done reading sX for this layer

        #pragma unroll
        for (int i = 0; i < 8; i++) {
            const int c = cg + 32*i;
            const float bias = Bl[c];
            float v[8];
            #pragma unroll
            for (int p = 0; p < 4; p++) {
                v[2*p]   = fmaxf(lo2(acc[i][p]) + bias, 0.f);
                v[2*p+1] = fmaxf(hi2(acc[i][p]) + bias, 0.f);
            }
            *(float4*)&sX[c*64 + qg*4]      = make_float4(v[0], v[1], v[2], v[3]);
            *(float4*)&sX[c*64 + 32 + qg*4] = make_float4(v[4], v[5], v[6], v[7]);
        }
        __syncthreads();
    }

    // ---- epilogue: final 3-channel layer + bilinear-border residual ----
    if (t < 192) {
        const int q = t / 3, o = t % 3;
        const int gq = blockIdx.x*QB + q;
        const int b  = gq / Qt;
        const float* wr = &s_w4[o*256];
        float a0 = 0.f, a1 = 0.f, a2 = 0.f, a3 = 0.f;
        #pragma unroll 4
        for (int k = 0; k < 256; k += 4) {
            a0 += wr[k]   * sX[(k)*64 + q];
            a1 += wr[k+1] * sX[(k+1)*64 + q];
            a2 += wr[k+2] * sX[(k+2)*64 + q];
            a3 += wr[k+3] * sX[(k+3)*64 + q];
        }
        float acc = b4[o] + (a0 + a1) + (a2 + a3);

        const float cy = coord[(size_t)gq*2 + 0];
        const float cx = coord[(size_t)gq*2 + 1];
        const float fy = ((cy + 1.f)*Ht - 1.f)*0.5f;
        const float fx = ((cx + 1.f)*Wt - 1.f)*0.5f;
        const float y0f = floorf(fy), x0f = floorf(fx);
        const float wy = fy - y0f, wx = fx - x0f;
        const int y0i = (int)fminf(fmaxf(y0f,       0.f), (float)(Ht-1));
        const int y1i = (int)fminf(fmaxf(y0f + 1.f, 0.f), (float)(Ht-1));
        const int x0i = (int)fminf(fmaxf(x0f,       0.f), (float)(Wt-1));
        const int x1i = (int)fminf(fmaxf(x0f + 1.f, 0.f), (float)(Wt-1));
        const float* ch = inp + ((size_t)(b*3 + o))*HWt;
        const float v00 = ch[(size_t)y0i*Wt + x0i];
        const float v01 = ch[(size_t)y0i*Wt + x1i];
        const float v10 = ch[(size_t)y1i*Wt + x0i];
        const float v11 = ch[(size_t)y1i*Wt + x1i];
        const float bil = v00*(1.f-wy)*(1.f-wx) + v01*(1.f-wy)*wx
                        + v10*wy*(1.f-wx)       + v11*wy*wx;
        out[(size_t)gq*3 + o] = acc + bil;
    }
}

// ---------------- launch ----------------
extern "C" void kernel_launch(void* const* d_in, const int* in_sizes, int n_in,
                              void* d_out, int out_size)
{
    const float* inp     = (const float*)d_in[0];
    const float* score   = (const float*)d_in[1];
    const float* coord   = (const float*)d_in[2];
    const float* cell    = (const float*)d_in[3];
    const float* coef_w  = (const float*)d_in[4];
    const float* coef_b  = (const float*)d_in[5];
    const float* freq_w  = (const float*)d_in[6];
    const float* freq_b  = (const float*)d_in[7];
    const float* phase_w = (const float*)d_in[8];
    const float* a1_w    = (const float*)d_in[9];
    const float* a1_b    = (const float*)d_in[10];
    const float* a2_w    = (const float*)d_in[11];
    const float* a2_b    = (const float*)d_in[12];
    const float* w0 = (const float*)d_in[13]; const float* b0 = (const float*)d_in[14];
    const float* w1 = (const float*)d_in[15]; const float* b1 = (const float*)d_in[16];
    const float* w2 = (const float*)d_in[17]; const float* b2 = (const float*)d_in[18];
    const float* w3 = (const float*)d_in[19]; const float* b3 = (const float*)d_in[20];
    const float* w4 = (const float*)d_in[21]; const float* b4 = (const float*)d_in[22];
    float* out = (float*)d_out;

    dim3 blk(16, 16, 1);
    dim3 grd(Wt/16, Ht/16, Bt);

    k_adapter1<<<grd, blk>>>(inp, a1_w, a1_b);
    k_adapter2_feat<<<grd, blk>>>(inp, score, a2_w, a2_b);

    cudaFuncSetAttribute(k_coef_freq, cudaFuncAttributeMaxDynamicSharedMemorySize, K3_SMEM);
    k_coef_freq<<<grd, blk, K3_SMEM>>>(coef_w, coef_b, freq_w, freq_b);

    cudaFuncSetAttribute(k_query, cudaFuncAttributeMaxDynamicSharedMemorySize, KQ_SMEM);
    k_query<<<(Bt*Qt)/QB, 256, KQ_SMEM>>>(inp, coord, cell, phase_w,
                                          w0, b0, w1, b1, w2, b2, w3, b3, w4, b4, out);
}

// round 15
// speedup vs baseline: 1.0711x; 1.0711x over previous
#include <cuda_runtime.h>
#include <cstdint>
#include <cstring>

#define Bt 4
#define Ht 192
#define Wt 192
#define HWt (Ht*Wt)
#define Qt 36864
#define PI_F 3.14159274f

// ---------------- scratch (device globals; no allocation allowed) ----------------
__device__ float g_t1[(size_t)Bt*128*HWt];      // adapter conv1 output (sin applied)
__device__ float g_feat[(size_t)Bt*9*HWt];      // [b][9][H][W]
__device__ float g_coefT[(size_t)Bt*HWt*256];   // [b][pix][256]
__device__ float g_freqT[(size_t)Bt*HWt*256];   // [b][pix][256]

// ---------------- f32x2 + cp.async helpers ----------------
__device__ __forceinline__ void fma2(unsigned long long& d, unsigned long long a, unsigned long long b) {
    asm("fma.rn.f32x2 %0, %1, %2, %0;" : "+l"(d) : "l"(a), "l"(b));
}
__device__ __forceinline__ unsigned long long dup2(float w) {
    unsigned long long r;
    asm("mov.b64 %0, {%1, %1};" : "=l"(r) : "f"(w));
    return r;
}
__device__ __forceinline__ unsigned long long pack2(float lo, float hi) {
    unsigned long long r;
    asm("mov.b64 %0, {%1, %2};" : "=l"(r) : "f"(lo), "f"(hi));
    return r;
}
__device__ __forceinline__ float lo2(unsigned long long v){ float2 f; memcpy(&f,&v,8); return f.x; }
__device__ __forceinline__ float hi2(unsigned long long v){ float2 f; memcpy(&f,&v,8); return f.y; }
__device__ __forceinline__ void cpa16(uint32_t s, const void* g) {
    asm volatile("cp.async.ca.shared.global [%0], [%1], 16;" :: "r"(s), "l"(g));
}
__device__ __forceinline__ void cpa_commit() { asm volatile("cp.async.commit_group;"); }
__device__ __forceinline__ void cpa_wait1() { asm volatile("cp.async.wait_group 1;"); }
__device__ __forceinline__ void cpa_wait0() { asm volatile("cp.async.wait_group 0;"); }

// ---------------- K1: adapter conv1: inp(3ch) -> sin(conv3x3) -> t1(128ch) ----------------
__global__ void k_adapter1(const float* __restrict__ inp,
                           const float* __restrict__ a1_w,
                           const float* __restrict__ a1_b)
{
    __shared__ float s_in[3][18][18];
    __shared__ float s_w[128*28];
    __shared__ float s_b[128];
    const int b = blockIdx.z;
    const int x0 = blockIdx.x*16, y0 = blockIdx.y*16;
    const int tx = threadIdx.x, ty = threadIdx.y;
    const int t = ty*16 + tx;

    for (int i = t; i < 128*27; i += 256) { int oc = i/27, r = i%27; s_w[oc*28+r] = a1_w[i]; }
    for (int i = t; i < 128; i += 256)    { s_b[i] = a1_b[i]; s_w[i*28+27] = 0.f; }
    for (int i = t; i < 3*18*18; i += 256) {
        int ic = i/324, r = i%324;
        int yy = y0 + r/18 - 1, xx = x0 + r%18 - 1;
        float v = 0.f;
        if (yy >= 0 && yy < Ht && xx >= 0 && xx < Wt)
            v = inp[((size_t)(b*3+ic))*HWt + (size_t)yy*Wt + xx];
        s_in[ic][r/18][r%18] = v;
    }
    __syncthreads();

    float f[28];
    #pragma unroll
    for (int ic = 0; ic < 3; ic++)
        #pragma unroll
        for (int ky = 0; ky < 3; ky++)
            #pragma unroll
            for (int kx = 0; kx < 3; kx++)
                f[ic*9 + ky*3 + kx] = s_in[ic][ty+ky][tx+kx];
    f[27] = 0.f;

    unsigned long long fp[14];
    #pragma unroll
    for (int j = 0; j < 14; j++) fp[j] = pack2(f[2*j], f[2*j+1]);

    const int x = x0 + tx, y = y0 + ty;
    const size_t obase = ((size_t)b*128)*HWt + (size_t)y*Wt + x;
    for (int oc = 0; oc < 128; oc++) {
        const ulonglong2* w2 = (const ulonglong2*)&s_w[oc*28];
        unsigned long long accA = 0ull, accB = 0ull;
        #pragma unroll
        for (int j = 0; j < 7; j++) {
            ulonglong2 w = w2[j];
            fma2(accA, w.x, fp[2*j]);
            fma2(accB, w.y, fp[2*j+1]);
        }
        float acc = s_b[oc] + lo2(accA) + hi2(accA) + lo2(accB) + hi2(accB);
        g_t1[obase + (size_t)oc*HWt] = __sinf(acc);
    }
}

// ---------------- K2: adapter conv2 (128->3) + sin, build feat[9] ----------------
__global__ void k_adapter2_feat(const float* __restrict__ inp,
                                const float* __restrict__ score,
                                const float* __restrict__ a2_w,
                                const float* __restrict__ a2_b)
{
    __shared__ float s_t[16][18][18];
    __shared__ float s_w[3*128*12];
    const int b = blockIdx.z;
    const int x0 = blockIdx.x*16, y0 = blockIdx.y*16;
    const int tx = threadIdx.x, ty = threadIdx.y;
    const int t = ty*16 + tx;

    for (int i = t; i < 3*128*9; i += 256) { int oi = i/9, r = i%9; s_w[oi*12+r] = a2_w[i]; }
    for (int i = t; i < 3*128; i += 256)   { s_w[i*12+9]=0.f; s_w[i*12+10]=0.f; s_w[i*12+11]=0.f; }

    float acc0 = a2_b[0], acc1 = a2_b[1], acc2 = a2_b[2];

    for (int ic0 = 0; ic0 < 128; ic0 += 16) {
        __syncthreads();
        for (int i = t; i < 16*324; i += 256) {
            int ic = i/324, r = i%324;
            int yy = y0 + r/18 - 1, xx = x0 + r%18 - 1;
            float v = 0.f;
            if (yy >= 0 && yy < Ht && xx >= 0 && xx < Wt)
                v = g_t1[((size_t)(b*128 + ic0 + ic))*HWt + (size_t)yy*Wt + xx];
            s_t[ic][r/18][r%18] = v;
        }
        __syncthreads();
        #pragma unroll
        for (int ic = 0; ic < 16; ic++) {
            float f[12];
            #pragma unroll
            for (int ky = 0; ky < 3; ky++)
                #pragma unroll
                for (int kx = 0; kx < 3; kx++)
                    f[ky*3+kx] = s_t[ic][ty+ky][tx+kx];
            f[9] = f[10] = f[11] = 0.f;
            unsigned long long fp[6];
            #pragma unroll
            for (int j = 0; j < 6; j++) fp[j] = pack2(f[2*j], f[2*j+1]);
            #pragma unroll
            for (int oc = 0; oc < 3; oc++) {
                const ulonglong2* w2 = (const ulonglong2*)&s_w[(oc*128 + ic0 + ic)*12];
                unsigned long long aA = 0ull, aB = 0ull;
                #pragma unroll
                for (int j = 0; j < 3; j++) {
                    ulonglong2 w = w2[j];
                    fma2(aA, w.x, fp[2*j]);
                    fma2(aB, w.y, fp[2*j+1]);
                }
                float a = lo2(aA) + hi2(aA) + lo2(aB) + hi2(aB);
                if (oc == 0) acc0 += a; else if (oc == 1) acc1 += a; else acc2 += a;
            }
        }
    }

    const int x = x0 + tx, y = y0 + ty;
    const size_t pix = (size_t)y*Wt + x;
    const size_t fb = (size_t)b*9*HWt;
    #pragma unroll
    for (int c = 0; c < 3; c++) {
        g_feat[fb + (size_t)c*HWt + pix]       = inp[((size_t)(b*3+c))*HWt + pix];
        g_feat[fb + (size_t)(3+c)*HWt + pix]   = score[((size_t)(b*3+c))*HWt + pix];
    }
    g_feat[fb + (size_t)6*HWt + pix] = __sinf(acc0);
    g_feat[fb + (size_t)7*HWt + pix] = __sinf(acc1);
    g_feat[fb + (size_t)8*HWt + pix] = __sinf(acc2);
}

// ---------------- K3: coef + freq conv (9 -> 512), f32x2 inner, transposed output (round-12) ----------------
#define K3_SMEM (512*84*4 + 512*4)
__global__ void __launch_bounds__(256) k_coef_freq(
    const float* __restrict__ coef_w, const float* __restrict__ coef_b,
    const float* __restrict__ freq_w, const float* __restrict__ freq_b)
{
    extern __shared__ float sm[];
    float* s_w = sm;           // [512][84]
    float* s_b = sm + 512*84;  // [512]
    const int b = blockIdx.z;
    const int x0 = blockIdx.x*16, y0 = blockIdx.y*16;
    const int t = threadIdx.y*16 + threadIdx.x;

    for (int i = t; i < 256*81; i += 256) {
        int oc = i/81, r = i%81;
        s_w[oc*84 + r]       = coef_w[i];
        s_w[(256+oc)*84 + r] = freq_w[i];
    }
    for (int i = t; i < 512; i += 256) {
        s_w[i*84+81] = 0.f; s_w[i*84+82] = 0.f; s_w[i*84+83] = 0.f;
        s_b[i] = (i < 256) ? coef_b[i] : freq_b[i-256];
    }
    __syncthreads();

    const int x = x0 + threadIdx.x, y = y0 + threadIdx.y;
    float f[84];
    #pragma unroll
    for (int ic = 0; ic < 9; ic++)
        #pragma unroll
        for (int ky = 0; ky < 3; ky++)
            #pragma unroll
            for (int kx = 0; kx < 3; kx++) {
                int yy = y + ky - 1, xx = x + kx - 1;
                float v = 0.f;
                if (yy >= 0 && yy < Ht && xx >= 0 && xx < Wt)
                    v = g_feat[((size_t)(b*9+ic))*HWt + (size_t)yy*Wt + xx];
                f[ic*9 + ky*3 + kx] = v;
            }
    f[81] = f[82] = f[83] = 0.f;

    unsigned long long fp[42];
    #pragma unroll
    for (int j = 0; j < 42; j++) fp[j] = pack2(f[2*j], f[2*j+1]);

    const size_t pix = (size_t)y*Wt + x;
    const size_t obase = ((size_t)b*HWt + pix)*256;
    #pragma unroll
    for (int half = 0; half < 2; half++) {
        float* dst = half ? g_freqT : g_coefT;
        for (int oc = 0; oc < 256; oc += 4) {
            float4 av;
            float* a = (float*)&av;
            #pragma unroll
            for (int u = 0; u < 4; u++) {
                int row = half*256 + oc + u;
                const ulonglong2* w2 = (const ulonglong2*)&s_w[row*84];
                unsigned long long accA = 0ull, accB = 0ull;
                #pragma unroll
                for (int j = 0; j < 21; j++) {
                    ulonglong2 w = w2[j];
                    fma2(accA, w.x, fp[2*j]);
                    fma2(accB, w.y, fp[2*j+1]);
                }
                a[u] = s_b[row] + lo2(accA) + hi2(accA) + lo2(accB) + hi2(accB);
            }
            *(float4*)&dst[obase + oc] = av;
        }
    }
}

// ---------------- K4: per-query sin/cos + MLP + bilinear residual ----------------
// Round-12 config + k-split epilogue over all 256 threads.
#define QB 64
#define KQ_SMEM ((256*64 + 2*256*20 + 256 + 768) * 4)

__global__ void __launch_bounds__(256, 2) k_query(
    const float* __restrict__ inp,
    const float* __restrict__ coord, const float* __restrict__ cell,
    const float* __restrict__ phase_w,
    const float* __restrict__ w0, const float* __restrict__ b0,
    const float* __restrict__ w1, const float* __restrict__ b1,
    const float* __restrict__ w2, const float* __restrict__ b2,
    const float* __restrict__ w3, const float* __restrict__ b3,
    const float* __restrict__ w4, const float* __restrict__ b4,
    float* __restrict__ out)
{
    extern __shared__ float sm[];
    float* sX   = sm;                    // 256*64
    float* sW0  = sX  + 256*64;          // 256*20
    float* sW1  = sW0 + 256*20;          // 256*20
    float* s_ph = sW1 + 256*20;          // 256
    float* s_w4 = s_ph + 256;            // 768

    const int t   = threadIdx.x;
    const int wid = t >> 5;
    const int l   = t & 31;
    const float* Ws[4] = {w0, w1, w2, w3};
    const float* Bs[4] = {b0, b1, b2, b3};

    auto stage = [&](const float* Wsrc, int tn, float* buf) {
        #pragma unroll
        for (int u = 0; u < 4; u++) {
            int c   = l + 32*u;
            int j   = c >> 2;
            int row = 4*wid + (j & 3) + 32*(j >> 2);
            int col = (c & 3)*4;
            cpa16((uint32_t)__cvta_generic_to_shared(&buf[row*20 + col]),
                  Wsrc + (size_t)row*256 + tn*16 + col);
        }
        cpa_commit();
    };

    stage(w0, 0, sW0);
    stage(w0, 1, sW1);

    s_ph[t] = phase_w[t];
    for (int i = t; i < 768; i += 256) s_w4[i] = w4[i];

    // ---- prologue: sincos features into sX[k][q] ----
    {
        const int q = t >> 2;
        const int ql = t & 3;
        const int gq = blockIdx.x*QB + q;
        const int b  = gq / Qt;

        const float cy = coord[(size_t)gq*2 + 0];
        const float cx = coord[(size_t)gq*2 + 1];
        const float ccy = fminf(fmaxf(cy, -0.999999f), 0.999999f);
        const float ccx = fminf(fmaxf(cx, -0.999999f), 0.999999f);
        const float fy = ((ccy + 1.f)*Ht - 1.f)*0.5f;
        const float fx = ((ccx + 1.f)*Wt - 1.f)*0.5f;
        const int iy = (int)fminf(fmaxf(rintf(fy), 0.f), (float)(Ht-1));
        const int ix = (int)fminf(fmaxf(rintf(fx), 0.f), (float)(Wt-1));
        const float qy = -1.f + (2.f*(float)iy + 1.f)/(float)Ht;
        const float qx = -1.f + (2.f*(float)ix + 1.f)/(float)Wt;
        const float rel0 = (cy - qy)*(float)Ht;
        const float rel1 = (cx - qx)*(float)Wt;
        const float rc0 = cell[(size_t)gq*2 + 0]*(float)Ht;
        const float rc1 = cell[(size_t)gq*2 + 1]*(float)Wt;
        const size_t base = ((size_t)b*HWt + (size_t)iy*Wt + ix)*256;

        __syncthreads();   // s_ph ready

        #pragma unroll
        for (int i = 0; i < 32; i++) {
            const int j = ql + 4*i;
            float2 fr = *(const float2*)&g_freqT[base + 2*j];
            float qf = fr.x*rel0 + fr.y*rel1 + s_ph[2*j]*rc0 + s_ph[2*j+1]*rc1;
            float sv, cv;
            __sincosf(PI_F*qf, &sv, &cv);
            float c0 = g_coefT[base + j];
            float c1 = g_coefT[base + 128 + j];
            sX[j*64 + q]         = c0*cv;
            sX[(128 + j)*64 + q] = c1*sv;
        }
    }
    __syncthreads();

    const int cg = t >> 3;               // 0..31 : channels cg, cg+32, ..., cg+224
    const int qg = t & 7;                // 0..7  : queries qg*4..+4 and 32+qg*4..+4

    #pragma unroll 1
    for (int L = 0; L < 4; L++) {
        const float* Bl = Bs[L];

        unsigned long long acc[8][4];
        #pragma unroll
        for (int i = 0; i < 8; i++)
            #pragma unroll
            for (int p = 0; p < 4; p++) acc[i][p] = 0ull;

        #pragma unroll 1
        for (int tile = 0; tile < 16; tile++) {
            const int g = L*16 + tile;
            if (g < 63) cpa_wait1();
            else        cpa_wait0();

            const float* sw = (g & 1) ? sW1 : sW0;
            const int kbase = tile*16;
            #pragma unroll
            for (int kk = 0; kk < 16; kk += 4) {
                float4 wv[8];
                #pragma unroll
                for (int i = 0; i < 8; i++)
                    wv[i] = *(const float4*)&sw[(cg + 32*i)*20 + kk];
                #pragma unroll
                for (int dk = 0; dk < 4; dk++) {
                    const int k = kbase + kk + dk;
                    ulonglong2 xa = *(const ulonglong2*)&sX[k*64 + qg*4];
                    ulonglong2 xb = *(const ulonglong2*)&sX[k*64 + 32 + qg*4];
                    #pragma unroll
                    for (int i = 0; i < 8; i++) {
                        float w = (dk == 0) ? wv[i].x : (dk == 1) ? wv[i].y
                                : (dk == 2) ? wv[i].z : wv[i].w;
                        unsigned long long wd = dup2(w);
                        fma2(acc[i][0], wd, xa.x);
                        fma2(acc[i][1], wd, xa.y);
                        fma2(acc[i][2], wd, xb.x);
                        fma2(acc[i][3], wd, xb.y);
                    }
                }
            }

            const int gn = g + 2;
            if (gn < 64)
                stage(Ws[gn >> 4], gn & 15, (g & 1) ? sW1 : sW0);
        }

        __syncthreads();   // all warps done reading sX for this layer

        #pragma unroll
        for (int i = 0; i < 8; i++) {
            const int c = cg + 32*i;
            const float bias = Bl[c];
            float v[8];
            #pragma unroll
            for (int p = 0; p < 4; p++) {
                v[2*p]   = fmaxf(lo2(acc[i][p]) + bias, 0.f);
                v[2*p+1] = fmaxf(hi2(acc[i][p]) + bias, 0.f);
            }
            *(float4*)&sX[c*64 + qg*4]      = make_float4(v[0], v[1], v[2], v[3]);
            *(float4*)&sX[c*64 + 32 + qg*4] = make_float4(v[4], v[5], v[6], v[7]);
        }
        __syncthreads();
    }
    // final activations now in sX

    // ---- epilogue: final 3-channel layer, 4-way k-split over all 256 threads ----
    {
        const int s = t >> 6;            // k-slice 0..3
        const int q = t & 63;
        float p0 = 0.f, p1 = 0.f, p2 = 0.f;
        const int k0 = s*64;
        #pragma unroll 8
        for (int k = k0; k < k0 + 64; k++) {
            float xv = sX[k*64 + q];
            p0 += xv * s_w4[k];
            p1 += xv * s_w4[256 + k];
            p2 += xv * s_w4[512 + k];
        }
        float* part = sW0;               // free now: 4*64*3 floats
        part[(s*64 + q)*3 + 0] = p0;
        part[(s*64 + q)*3 + 1] = p1;
        part[(s*64 + q)*3 + 2] = p2;
    }
    __syncthreads();

    if (t < 192) {
        const int q = t / 3, o = t % 3;
        const int gq = blockIdx.x*QB + q;
        const int b  = gq / Qt;
        const float* part = sW0;
        float acc = b4[o] + (part[(q)*3 + o]       + part[(64 + q)*3 + o])
                          + (part[(128 + q)*3 + o] + part[(192 + q)*3 + o]);

        const float cy = coord[(size_t)gq*2 + 0];
        const float cx = coord[(size_t)gq*2 + 1];
        const float fy = ((cy + 1.f)*Ht - 1.f)*0.5f;
        const float fx = ((cx + 1.f)*Wt - 1.f)*0.5f;
        const float y0f = floorf(fy), x0f = floorf(fx);
        const float wy = fy - y0f, wx = fx - x0f;
        const int y0i = (int)fminf(fmaxf(y0f,       0.f), (float)(Ht-1));
        const int y1i = (int)fminf(fmaxf(y0f + 1.f, 0.f), (float)(Ht-1));
        const int x0i = (int)fminf(fmaxf(x0f,       0.f), (float)(Wt-1));
        const int x1i = (int)fminf(fmaxf(x0f + 1.f, 0.f), (float)(Wt-1));
        const float* ch = inp + ((size_t)(b*3 + o))*HWt;
        const float v00 = ch[(size_t)y0i*Wt + x0i];
        const float v01 = ch[(size_t)y0i*Wt + x1i];
        const float v10 = ch[(size_t)y1i*Wt + x0i];
        const float v11 = ch[(size_t)y1i*Wt + x1i];
        const float bil = v00*(1.f-wy)*(1.f-wx) + v01*(1.f-wy)*wx
                        + v10*wy*(1.f-wx)       + v11*wy*wx;
        out[(size_t)gq*3 + o] = acc + bil;
    }
}

// ---------------- launch ----------------
extern "C" void kernel_launch(void* const* d_in, const int* in_sizes, int n_in,
                              void* d_out, int out_size)
{
    const float* inp     = (const float*)d_in[0];
    const float* score   = (const float*)d_in[1];
    const float* coord   = (const float*)d_in[2];
    const float* cell    = (const float*)d_in[3];
    const float* coef_w  = (const float*)d_in[4];
    const float* coef_b  = (const float*)d_in[5];
    const float* freq_w  = (const float*)d_in[6];
    const float* freq_b  = (const float*)d_in[7];
    const float* phase_w = (const float*)d_in[8];
    const float* a1_w    = (const float*)d_in[9];
    const float* a1_b    = (const float*)d_in[10];
    const float* a2_w    = (const float*)d_in[11];
    const float* a2_b    = (const float*)d_in[12];
    const float* w0 = (const float*)d_in[13]; const float* b0 = (const float*)d_in[14];
    const float* w1 = (const float*)d_in[15]; const float* b1 = (const float*)d_in[16];
    const float* w2 = (const float*)d_in[17]; const float* b2 = (const float*)d_in[18];
    const float* w3 = (const float*)d_in[19]; const float* b3 = (const float*)d_in[20];
    const float* w4 = (const float*)d_in[21]; const float* b4 = (const float*)d_in[22];
    float* out = (float*)d_out;

    dim3 blk(16, 16, 1);
    dim3 grd(Wt/16, Ht/16, Bt);

    k_adapter1<<<grd, blk>>>(inp, a1_w, a1_b);
    k_adapter2_feat<<<grd, blk>>>(inp, score, a2_w, a2_b);

    cudaFuncSetAttribute(k_coef_freq, cudaFuncAttributeMaxDynamicSharedMemorySize, K3_SMEM);
    k_coef_freq<<<grd, blk, K3_SMEM>>>(coef_w, coef_b, freq_w, freq_b);

    cudaFuncSetAttribute(k_query, cudaFuncAttributeMaxDynamicSharedMemorySize, KQ_SMEM);
    k_query<<<(Bt*Qt)/QB, 256, KQ_SMEM>>>(inp, coord, cell, phase_w,
                                          w0, b0, w1, b1, w2, b2, w3, b3, w4, b4, out);
}